// round 2
// baseline (speedup 1.0000x reference)
#include <cuda_runtime.h>
#include <cstdint>

// ---------------------------------------------------------------------------
// Problem constants
//   queries:    (16, 128, 12, 8, 192) f32   [b, u, w, n, h]
//   keys:       (16, 128, 24, 8, 192) f32   [b, u, c, n, h]
//   pos_proj_w: (1536, 1536) f32
//   out:        (16, 8, 128, 12, 24) f32    [b, n, u, w, c]
// out[b,n,u,w,c] = sum_h Q*K  +  (0 <= c-w <= 12 ? sum_h Q*S[c-w] : 0)
// where S = (sin-emb @ pos_proj_w) reshaped to [13, 8, 192].
// ---------------------------------------------------------------------------

#define NB      16
#define NU      128
#define NW      12
#define NC      24
#define NH      8
#define HD      192
#define CHN     1536          // NH*HD
#define NF      13            // relative positions
#define NCE     37            // NC + NF (fused extended-key dim)

#define KPARTS  8
#define KPER    (CHN / KPARTS)   // 192

// h-chunking for main kernel
#define HCH     64
#define CST     68                       // chunk row stride (floats): 68 % 32 == 4 -> conflict free
#define ROWS_PER_HEAD 52                 // 12 Q rows + 40 Kext rows (37 valid + 3 pad)
#define HEAD_SMEM (ROWS_PER_HEAD * CST)  // floats per head (3536; 14144 B, 16B-aligned)
#define SMEM_BYTES (NH * HEAD_SMEM * 4)  // 113152 B

// scratch (device globals; no allocation allowed)
__device__ float g_part[KPARTS * NF * CHN];
__device__ float g_S[NF * CHN];          // [f][n*192+h]

// packed f32x2 FMA: d = a*b + d  (two independent fp32 lanes, one instruction)
__device__ __forceinline__ void ffma2(unsigned long long& d,
                                      unsigned long long a,
                                      unsigned long long b) {
    asm("fma.rn.f32x2 %0, %1, %2, %0;" : "+l"(d) : "l"(a), "l"(b));
}

// ---------------------------------------------------------------------------
// Kernel 1: partial projection  part[p][f][col] = sum_{k in part} sin[f,k]*W[k,col]
// grid (12, KPARTS), block 128 (one thread per output column)
// ---------------------------------------------------------------------------
__global__ void proj_partial_kernel(const float* __restrict__ W,
                                    float* __restrict__ part) {
    const float LTI = 9.210340372f / 767.0f;   // log(10000) / (768-1)
    int pid = blockIdx.y;
    int col = blockIdx.x * 128 + threadIdx.x;

    __shared__ float st[NF * 64];
    float acc[NF];
#pragma unroll
    for (int f = 0; f < NF; f++) acc[f] = 0.0f;

    int kbase = pid * KPER;
    for (int t = 0; t < KPER; t += 64) {
        int k0 = kbase + t;
        __syncthreads();
        for (int i = threadIdx.x; i < NF * 64; i += 128) {
            int f  = i >> 6;
            int kk = i & 63;
            int k  = k0 + kk;
            float pos = (float)(12 - f);               // positions 12..0
            int idx = (k < 768) ? k : (k - 768);
            float invts = expf(-(float)idx * LTI);
            float sc = pos * invts;
            st[i] = (k < 768) ? sinf(sc) : cosf(sc);
        }
        __syncthreads();
#pragma unroll 4
        for (int kk = 0; kk < 64; kk++) {
            float w = W[(k0 + kk) * CHN + col];
#pragma unroll
            for (int f = 0; f < NF; f++)
                acc[f] = fmaf(st[f * 64 + kk], w, acc[f]);
        }
    }
#pragma unroll
    for (int f = 0; f < NF; f++)
        part[pid * (NF * CHN) + f * CHN + col] = acc[f];
}

// ---------------------------------------------------------------------------
// Kernel 2: reduce the k-partials into g_S
// ---------------------------------------------------------------------------
__global__ void proj_reduce_kernel(const float* __restrict__ part,
                                   float* __restrict__ S) {
    int i = blockIdx.x * 256 + threadIdx.x;
    if (i < NF * CHN) {
        float s = 0.0f;
#pragma unroll
        for (int p = 0; p < KPARTS; p++) s += part[p * (NF * CHN) + i];
        S[i] = s;
    }
}

// ---------------------------------------------------------------------------
// Kernel 3: main fused attention-logits kernel.
// One block per (b,u); 8 warps, warp n handles head n.
// Per head: O[12,37] = Q[12,192] @ [K(24 rows); S(13 rows)]^T, streamed through
// smem in 3 chunks of h=64, 3x5 per-lane register tile, f32x2 accumulators.
// Relative shift folded into the epilogue via per-warp smem staging.
// ---------------------------------------------------------------------------
__global__ void __launch_bounds__(256, 2)
main_kernel(const float* __restrict__ Q,
            const float* __restrict__ K,
            const float* __restrict__ S,
            float* __restrict__ out) {
    extern __shared__ float sm[];

    const int bu   = blockIdx.x;          // b*128 + u
    const int tid  = threadIdx.x;
    const int warp = tid >> 5;            // head index n
    const int lane = tid & 31;
    const int wg   = lane & 3;            // w group: rows wg, wg+4, wg+8
    const int cg   = lane >> 2;           // c group: cols cg + 8*j

    unsigned long long acc[3][5];
#pragma unroll
    for (int i = 0; i < 3; i++)
#pragma unroll
        for (int j = 0; j < 5; j++) acc[i][j] = 0ULL;

    float* Qh = sm + warp * HEAD_SMEM;      // rows 0..11
    float* Kh = Qh + 12 * CST;              // extended-key rows 0..39 (37 valid)

    for (int ch = 0; ch < 3; ch++) {
        const int h0 = ch * HCH;
        __syncthreads();
        // cooperative load: 8 heads x 49 rows x 16 float4 segments (coalesced:
        // 16 consecutive threads fetch one contiguous 256B row-chunk)
        for (int i = tid; i < NH * 49 * 16; i += 256) {
            int row = i >> 4;
            int seg = i & 15;
            int n = row / 49;
            int r = row - n * 49;                 // 0..11 Q | 12..35 K | 36..48 S
            const float* src;
            if (r < 12)        src = Q + ((bu * NW + r) * NH + n) * HD;
            else if (r < 36)   src = K + ((bu * NC + (r - 12)) * NH + n) * HD;
            else               src = S + ((r - 36) * NH + n) * HD;
            float4 v = *reinterpret_cast<const float4*>(src + h0 + seg * 4);
            *reinterpret_cast<float4*>(sm + n * HEAD_SMEM + r * CST + seg * 4) = v;
        }
        __syncthreads();

#pragma unroll 2
        for (int h = 0; h < HCH; h += 4) {
            ulonglong2 q0 = *reinterpret_cast<const ulonglong2*>(Qh + (wg    ) * CST + h);
            ulonglong2 q1 = *reinterpret_cast<const ulonglong2*>(Qh + (wg + 4) * CST + h);
            ulonglong2 q2 = *reinterpret_cast<const ulonglong2*>(Qh + (wg + 8) * CST + h);
            ulonglong2 kv[5];
#pragma unroll
            for (int j = 0; j < 5; j++)
                kv[j] = *reinterpret_cast<const ulonglong2*>(Kh + (cg + 8 * j) * CST + h);
#pragma unroll
            for (int j = 0; j < 5; j++) {
                ffma2(acc[0][j], q0.x, kv[j].x);
                ffma2(acc[0][j], q0.y, kv[j].y);
                ffma2(acc[1][j], q1.x, kv[j].x);
                ffma2(acc[1][j], q1.y, kv[j].y);
                ffma2(acc[2][j], q2.x, kv[j].x);
                ffma2(acc[2][j], q2.y, kv[j].y);
            }
        }
    }

    // Epilogue: stage O[12][37] in this warp's own smem region (disjoint per
    // head -> warp-level sync suffices), then apply the relative shift:
    //   out[w,c] = O[w,c] + (0 <= c-w <= 12 ? O[w, 24 + (c-w)] : 0)
    float* Osm = Qh;   // 12*37 = 444 floats fits in the 12*68 Q area
#pragma unroll
    for (int i = 0; i < 3; i++) {
        int w = wg + 4 * i;
#pragma unroll
        for (int j = 0; j < 5; j++) {
            int ce = cg + 8 * j;
            if (ce < NCE) {                       // cols 37..39 are dead pad
                float2 p = *reinterpret_cast<float2*>(&acc[i][j]);
                Osm[w * NCE + ce] = p.x + p.y;
            }
        }
    }
    __syncwarp();

    const int b = bu >> 7;
    const int u = bu & 127;
    float* op = out + (size_t)(b * 1024 + warp * 128 + u) * (NW * NC);
#pragma unroll
    for (int t = 0; t < 9; t++) {
        int idx = t * 32 + lane;          // 0..287, coalesced stores
        int w = idx / NC;
        int c = idx - w * NC;
        int d = c - w;
        float v = Osm[w * NCE + c];
        if ((unsigned)d <= 12u) v += Osm[w * NCE + NC + d];
        op[idx] = v;
    }
}

// ---------------------------------------------------------------------------
extern "C" void kernel_launch(void* const* d_in, const int* in_sizes, int n_in,
                              void* d_out, int out_size) {
    const float* q = (const float*)d_in[0];
    const float* k = (const float*)d_in[1];
    const float* w = (const float*)d_in[2];
    float* out = (float*)d_out;

    float* part_ptr;
    float* s_ptr;
    cudaGetSymbolAddress((void**)&part_ptr, g_part);
    cudaGetSymbolAddress((void**)&s_ptr, g_S);

    // Idempotent, deterministic, capture-safe (host-side attribute only).
    cudaFuncSetAttribute(main_kernel,
                         cudaFuncAttributeMaxDynamicSharedMemorySize,
                         SMEM_BYTES);

    proj_partial_kernel<<<dim3(CHN / 128, KPARTS), 128>>>(w, part_ptr);
    proj_reduce_kernel<<<(NF * CHN + 255) / 256, 256>>>(part_ptr, s_ptr);
    main_kernel<<<NB * NU, 256, SMEM_BYTES>>>(q, k, s_ptr, out);
}

// round 11
// speedup vs baseline: 2.2680x; 2.2680x over previous
#include <cuda_runtime.h>
#include <cstdint>

// ---------------------------------------------------------------------------
// Problem constants
//   queries:    (16, 128, 12, 8, 192) f32   [b, u, w, n, h]
//   keys:       (16, 128, 24, 8, 192) f32   [b, u, c, n, h]
//   pos_proj_w: (1536, 1536) f32
//   out:        (16, 8, 128, 12, 24) f32    [b, n, u, w, c]
// out[b,n,u,w,c] = sum_h Q*K  +  (0 <= c-w <= 12 ? sum_h Q*S[c-w] : 0)
// where S = (sin-emb @ pos_proj_w) reshaped to [13, 8, 192].
// ---------------------------------------------------------------------------

#define NB      16
#define NU      128
#define NW      12
#define NC      24
#define NH      8
#define HD      192
#define CHN     1536          // NH*HD
#define NF      13            // relative positions
#define NCE     37            // NC + NF (fused extended-key dim)

#define KPARTS  16
#define KPER    (CHN / KPARTS)   // 96

// h-chunking for main kernel
#define HCH     64
#define CST     68                       // chunk row stride (floats): 68 % 32 == 4 -> conflict free
#define ROWS_PER_HEAD 52                 // 12 Q rows + 40 Kext rows (37 valid + 3 pad)
#define HEAD_SMEM (ROWS_PER_HEAD * CST)  // floats per head (3536; 14144 B, 16B-aligned)
#define SMEM_BYTES (NH * HEAD_SMEM * 4)  // 113152 B -> 2 CTAs/SM (inter-CTA overlap)

// scratch (device globals; no allocation allowed)
__device__ float g_part[KPARTS * NF * CHN];
__device__ float g_S[NF * CHN];          // [f][n*192+h]

// packed f32x2 FMA: d = a*b + d  (two independent fp32 lanes, one instruction)
__device__ __forceinline__ void ffma2(unsigned long long& d,
                                      unsigned long long a,
                                      unsigned long long b) {
    asm("fma.rn.f32x2 %0, %1, %2, %0;" : "+l"(d) : "l"(a), "l"(b));
}

// async 16B global->shared copy (LDGSTS): no register dependency, high MLP
__device__ __forceinline__ void cp16(uint32_t smem_dst, const void* gmem_src) {
    asm volatile("cp.async.cg.shared.global [%0], [%1], 16;"
                 :: "r"(smem_dst), "l"(gmem_src));
}
__device__ __forceinline__ void cp_commit_wait_all() {
    asm volatile("cp.async.commit_group;");
    asm volatile("cp.async.wait_group 0;");
}
__device__ __forceinline__ uint32_t smem_u32(const void* p) {
    uint32_t a;
    asm("{ .reg .u64 t; cvta.to.shared.u64 t, %1; cvt.u32.u64 %0, t; }"
        : "=r"(a) : "l"(p));
    return a;
}

// ---------------------------------------------------------------------------
// Kernel 1: partial projection  part[p][f][col] = sum_{k in part} sin[f,k]*W[k,col]
// grid (12, KPARTS), block 128 (one thread per output column).
// Whole 13 x 96 sin-emb slab staged in smem once; W loop unrolled x8 -> MLP 8.
// ---------------------------------------------------------------------------
__global__ void proj_partial_kernel(const float* __restrict__ W,
                                    float* __restrict__ part) {
    const float LTI = 9.210340372f / 767.0f;   // log(10000) / (768-1)
    const int pid = blockIdx.y;
    const int col = blockIdx.x * 128 + threadIdx.x;
    const int kbase = pid * KPER;

    __shared__ float st[NF * KPER];
    for (int i = threadIdx.x; i < NF * KPER; i += 128) {
        int f  = i / KPER;
        int kk = i - f * KPER;
        int k  = kbase + kk;
        float pos = (float)(12 - f);               // positions 12..0
        int idx = (k < 768) ? k : (k - 768);
        float invts = expf(-(float)idx * LTI);
        float sc = pos * invts;
        st[i] = (k < 768) ? sinf(sc) : cosf(sc);
    }
    __syncthreads();

    float acc[NF];
#pragma unroll
    for (int f = 0; f < NF; f++) acc[f] = 0.0f;

#pragma unroll 8
    for (int kk = 0; kk < KPER; kk++) {
        float w = W[(kbase + kk) * CHN + col];
#pragma unroll
        for (int f = 0; f < NF; f++)
            acc[f] = fmaf(st[f * KPER + kk], w, acc[f]);
    }
#pragma unroll
    for (int f = 0; f < NF; f++)
        part[pid * (NF * CHN) + f * CHN + col] = acc[f];
}

// ---------------------------------------------------------------------------
// Kernel 2: reduce the k-partials into g_S
// ---------------------------------------------------------------------------
__global__ void proj_reduce_kernel(const float* __restrict__ part,
                                   float* __restrict__ S) {
    int i = blockIdx.x * 256 + threadIdx.x;
    if (i < NF * CHN) {
        float s = 0.0f;
#pragma unroll
        for (int p = 0; p < KPARTS; p++) s += part[p * (NF * CHN) + i];
        S[i] = s;
    }
}

// ---------------------------------------------------------------------------
// Kernel 3: main fused attention-logits kernel.
// One block per (b,u); 8 warps, warp n handles head n.
// Per head: O[12,37] = Q[12,192] @ [K(24 rows); S(13 rows)]^T, streamed through
// smem in 3 chunks of h=64 via cp.async (fire-and-forget -> DRAM-throughput
// bound instead of LDG->STS latency bound). 3x5 per-lane register tile,
// f32x2 accumulators. Relative shift folded into the epilogue.
// ---------------------------------------------------------------------------
__global__ void __launch_bounds__(256, 2)
main_kernel(const float* __restrict__ Q,
            const float* __restrict__ K,
            const float* __restrict__ S,
            float* __restrict__ out) {
    extern __shared__ float sm[];

    const int bu   = blockIdx.x;          // b*128 + u
    const int tid  = threadIdx.x;
    const int warp = tid >> 5;            // head index n
    const int lane = tid & 31;
    const int wg   = lane & 3;            // w group: rows wg, wg+4, wg+8
    const int cg   = lane >> 2;           // c group: cols cg + 8*j

    const uint32_t sm_base = smem_u32(sm);
    const int b = bu >> 7;
    const int u = bu & 127;
    float* op = out + (size_t)(b * 1024 + warp * 128 + u) * (NW * NC);

    unsigned long long acc[3][5];
#pragma unroll
    for (int i = 0; i < 3; i++)
#pragma unroll
        for (int j = 0; j < 5; j++) acc[i][j] = 0ULL;

    float* Qh = sm + warp * HEAD_SMEM;      // rows 0..11
    float* Kh = Qh + 12 * CST;              // extended-key rows 0..39 (37 valid)

    for (int ch = 0; ch < 3; ch++) {
        const int h0 = ch * HCH;
        __syncthreads();     // previous chunk fully consumed before overwrite
        // cooperative async fill: 8 heads x 49 rows x 16 float4 segments
        // (16 consecutive threads fetch one contiguous 256B row-chunk)
        for (int i = tid; i < NH * 49 * 16; i += 256) {
            int row = i >> 4;
            int seg = i & 15;
            int n = row / 49;
            int r = row - n * 49;                 // 0..11 Q | 12..35 K | 36..48 S
            const float* src;
            if (r < 12)        src = Q + ((bu * NW + r) * NH + n) * HD;
            else if (r < 36)   src = K + ((bu * NC + (r - 12)) * NH + n) * HD;
            else               src = S + ((r - 36) * NH + n) * HD;
            cp16(sm_base + (uint32_t)(n * HEAD_SMEM + r * CST + seg * 4) * 4u,
                 src + h0 + seg * 4);
        }
        cp_commit_wait_all();
        __syncthreads();

#pragma unroll 2
        for (int h = 0; h < HCH; h += 4) {
            ulonglong2 q0 = *reinterpret_cast<const ulonglong2*>(Qh + (wg    ) * CST + h);
            ulonglong2 q1 = *reinterpret_cast<const ulonglong2*>(Qh + (wg + 4) * CST + h);
            ulonglong2 q2 = *reinterpret_cast<const ulonglong2*>(Qh + (wg + 8) * CST + h);
            ulonglong2 kv[5];
#pragma unroll
            for (int j = 0; j < 5; j++)
                kv[j] = *reinterpret_cast<const ulonglong2*>(Kh + (cg + 8 * j) * CST + h);
#pragma unroll
            for (int j = 0; j < 5; j++) {
                ffma2(acc[0][j], q0.x, kv[j].x);
                ffma2(acc[0][j], q0.y, kv[j].y);
                ffma2(acc[1][j], q1.x, kv[j].x);
                ffma2(acc[1][j], q1.y, kv[j].y);
                ffma2(acc[2][j], q2.x, kv[j].x);
                ffma2(acc[2][j], q2.y, kv[j].y);
            }
        }
    }

    // Epilogue: stage O[12][37] in this warp's own smem region (disjoint per
    // head -> warp-level sync suffices), then apply the relative shift:
    //   out[w,c] = O[w,c] + (0 <= c-w <= 12 ? O[w, 24 + (c-w)] : 0)
    float* Osm = Qh;   // 12*37 = 444 floats fits in the 12*68 Q area
#pragma unroll
    for (int i = 0; i < 3; i++) {
        int w = wg + 4 * i;
#pragma unroll
        for (int j = 0; j < 5; j++) {
            int ce = cg + 8 * j;
            if (ce < NCE) {                       // cols 37..39 are dead pad
                float2 p = *reinterpret_cast<float2*>(&acc[i][j]);
                Osm[w * NCE + ce] = p.x + p.y;
            }
        }
    }
    __syncwarp();

#pragma unroll
    for (int t = 0; t < 9; t++) {
        int idx = t * 32 + lane;          // 0..287, coalesced stores
        int w = idx / NC;
        int c = idx - w * NC;
        int d = c - w;
        float v = Osm[w * NCE + c];
        if ((unsigned)d <= 12u) v += Osm[w * NCE + NC + d];
        op[idx] = v;
    }
}

// ---------------------------------------------------------------------------
extern "C" void kernel_launch(void* const* d_in, const int* in_sizes, int n_in,
                              void* d_out, int out_size) {
    const float* q = (const float*)d_in[0];
    const float* k = (const float*)d_in[1];
    const float* w = (const float*)d_in[2];
    float* out = (float*)d_out;

    float* part_ptr;
    float* s_ptr;
    cudaGetSymbolAddress((void**)&part_ptr, g_part);
    cudaGetSymbolAddress((void**)&s_ptr, g_S);

    // Idempotent, deterministic, capture-safe (host-side attribute only).
    cudaFuncSetAttribute(main_kernel,
                         cudaFuncAttributeMaxDynamicSharedMemorySize,
                         SMEM_BYTES);

    proj_partial_kernel<<<dim3(CHN / 128, KPARTS), 128>>>(w, part_ptr);
    proj_reduce_kernel<<<(NF * CHN + 255) / 256, 256>>>(part_ptr, s_ptr);
    main_kernel<<<NB * NU, 256, SMEM_BYTES>>>(q, k, s_ptr, out);
}